// round 10
// baseline (speedup 1.0000x reference)
#include <cuda_runtime.h>
#include <cstdint>

// FineMatching: per match m (grid.x):
//   sims[l][s] = dot(x0[m,l,:], x1[m,s,:]) / 128   (64x64x128 GEMM, 3xTF32 mma.sync)
//   heatmap    = softmax_l(sims) * softmax_s(sims)
//   masked argmax -> idx_l, idx_s, biases
//
// d_out (f32): [ heatmap M*4096 | idx_l M | idx_s M | biases0 2M | biases1 2M ]
//
// Round-10: 256 threads, 8 warps = 4 col-slabs x 2 K-halves. Warp (wc,kh)
// computes full 64 x 16 slab over kt in [kh*8, kh*8+8); partial accumulators
// merged via smem exchange (overlaid on A-hi plane). Same ldsm/LDS traffic as
// round-7 (best), 2x warps/SMSP. A split hi/lo at staging; B raw, split in regs.

#define NTHREADS 256

// ---- smem byte offsets ----
#define OFF_AH 0                    // A hi plane, 64 x 512B, XOR-swizzled (exchange overlays after GEMM)
#define OFF_AL 32768                // A lo plane
#define OFF_B  65536                // B raw f32, swizzled
#define OFF_RP 98304                // row partials: 64 x 4 f32
#define OFF_CP (OFF_RP + 1024)      // col partials: 2 x 64 f32
#define OFF_RI (OFF_CP + 512)       // rinv 64 f32
#define OFF_CI (OFF_RI + 256)       // cinv 64 f32
#define OFF_RV (OFF_CI + 256)       // 8 f32
#define OFF_RX (OFF_RV + 32)        // 8 i32
#define SMEM_BYTES (OFF_RX + 32)

__device__ __forceinline__ uint32_t smem_u32(const void* p) {
    uint32_t a;
    asm("{ .reg .u64 t; cvta.to.shared.u64 t, %1; cvt.u32.u64 %0, t; }" : "=r"(a) : "l"(p));
    return a;
}

__device__ __forceinline__ uint32_t f2tf32(float f) {
    uint32_t r;
    asm("cvt.rna.tf32.f32 %0, %1;" : "=r"(r) : "f"(f));
    return r;
}

__device__ __forceinline__ void split_tf32(float f, uint32_t& hi, uint32_t& lo) {
    hi = f2tf32(f);
    float r = f - __uint_as_float(hi);
    lo = f2tf32(r);
}

__device__ __forceinline__ void ldsm_x4(uint32_t& r0, uint32_t& r1, uint32_t& r2,
                                        uint32_t& r3, uint32_t addr) {
    asm volatile("ldmatrix.sync.aligned.m8n8.x4.shared.b16 {%0,%1,%2,%3}, [%4];"
                 : "=r"(r0), "=r"(r1), "=r"(r2), "=r"(r3) : "r"(addr));
}

__device__ __forceinline__ void mma_tf32(float& d0, float& d1, float& d2, float& d3,
                                         uint32_t a0, uint32_t a1, uint32_t a2, uint32_t a3,
                                         uint32_t b0, uint32_t b1) {
    asm volatile(
        "mma.sync.aligned.m16n8k8.row.col.f32.tf32.tf32.f32 "
        "{%0,%1,%2,%3}, {%4,%5,%6,%7}, {%8,%9}, {%0,%1,%2,%3};"
        : "+f"(d0), "+f"(d1), "+f"(d2), "+f"(d3)
        : "r"(a0), "r"(a1), "r"(a2), "r"(a3), "r"(b0), "r"(b1));
}

__device__ __forceinline__ bool inner_mask(int p) {
    int y = p >> 3, x = p & 7;
    return (y >= 1) & (y <= 6) & (x >= 1) & (x <= 6);
}

__global__ void __launch_bounds__(NTHREADS, 2)
fm_kernel(const float* __restrict__ x0, const float* __restrict__ x1,
          float* __restrict__ hm, float* __restrict__ oil,
          float* __restrict__ ois, float* __restrict__ ob0,
          float* __restrict__ ob1) {
    extern __shared__ char sm[];
    float* rowpart = (float*)(sm + OFF_RP);
    float* colpart = (float*)(sm + OFF_CP);
    float* rinv_s  = (float*)(sm + OFF_RI);
    float* cinv_s  = (float*)(sm + OFF_CI);
    float* redv    = (float*)(sm + OFF_RV);
    int*   redi    = (int*)(sm + OFF_RX);

    const int m    = blockIdx.x;
    const int tid  = threadIdx.x;
    const int warp = tid >> 5;
    const int lane = tid & 31;
    const int g    = lane >> 2;
    const int tig  = lane & 3;
    const int wc   = warp & 3;          // col quarter (16 cols)
    const int kh   = warp >> 2;         // K half

    // ---- stage: A split hi/lo; B raw. XOR-chunk swizzled ----
    {
        const float4* p0 = (const float4*)(x0 + (size_t)m * 8192);
        const float4* p1 = (const float4*)(x1 + (size_t)m * 8192);
        uint4*  ahv = (uint4*)(sm + OFF_AH);
        uint4*  alv = (uint4*)(sm + OFF_AL);
        float4* bv  = (float4*)(sm + OFF_B);
#pragma unroll
        for (int it = 0; it < 8; it++) {
            int i = tid + it * NTHREADS;
            int row = i >> 5;
            int ch  = i & 31;
            int pch = ch ^ (row & 7);
            float4 a4 = p0[i];
            float4 b4 = p1[i];
            uint4 hi4, lo4;
            split_tf32(a4.x, hi4.x, lo4.x);
            split_tf32(a4.y, hi4.y, lo4.y);
            split_tf32(a4.z, hi4.z, lo4.z);
            split_tf32(a4.w, hi4.w, lo4.w);
            ahv[row * 32 + pch] = hi4;
            alv[row * 32 + pch] = lo4;
            bv[row * 32 + pch]  = b4;
        }
    }
    __syncthreads();

    // ---- GEMM: warp (wc,kh) -> partial sims[0:64, wc*16:+16] over K half ----
    float acc[4][2][4];
#pragma unroll
    for (int mt = 0; mt < 4; mt++)
#pragma unroll
        for (int nt = 0; nt < 2; nt++)
#pragma unroll
            for (int qq = 0; qq < 4; qq++) acc[mt][nt][qq] = 0.0f;

    const uint32_t smb = smem_u32(sm);

    const int qm = lane >> 3;
    const int rm = lane & 7;
    const uint32_t kq = (uint32_t)((qm >> 1) << 4);
    uint32_t abase[4], axm[4];
#pragma unroll
    for (int mt = 0; mt < 4; mt++) {
        int row = mt * 16 + ((qm & 1) << 3) + rm;
        abase[mt] = smb + OFF_AH + row * 512;
        axm[mt]   = (uint32_t)((row & 7) << 4);
    }
    uint32_t bbase[2], bswz[2];
#pragma unroll
    for (int nt = 0; nt < 2; nt++) {
        int row = wc * 16 + nt * 8 + g;
        bbase[nt] = OFF_B + row * 512 + tig * 4;
        bswz[nt]  = (uint32_t)((row & 7) << 4);
    }

    const int kt0 = kh * 8;
#pragma unroll
    for (int ki = 0; ki < 8; ki++) {
        uint32_t c0 = (uint32_t)((kt0 + ki) << 5);
        uint32_t c1 = c0 + 16;
        uint32_t koff = c0 | kq;
        uint32_t bh[2][2], bl[2][2];
#pragma unroll
        for (int nt = 0; nt < 2; nt++) {
            float f0 = *(const float*)(sm + bbase[nt] + (c0 ^ bswz[nt]));
            float f1 = *(const float*)(sm + bbase[nt] + (c1 ^ bswz[nt]));
            split_tf32(f0, bh[nt][0], bl[nt][0]);
            split_tf32(f1, bh[nt][1], bl[nt][1]);
        }
#pragma unroll
        for (int mt = 0; mt < 4; mt++) {
            uint32_t ad = abase[mt] + (koff ^ axm[mt]);
            uint32_t ah0, ah1, ah2, ah3, al0, al1, al2, al3;
            ldsm_x4(ah0, ah1, ah2, ah3, ad);
            ldsm_x4(al0, al1, al2, al3, ad + 32768);
#pragma unroll
            for (int nt = 0; nt < 2; nt++) {
                float* d = acc[mt][nt];
                mma_tf32(d[0], d[1], d[2], d[3], al0, al1, al2, al3, bh[nt][0], bh[nt][1]);
                mma_tf32(d[0], d[1], d[2], d[3], ah0, ah1, ah2, ah3, bl[nt][0], bl[nt][1]);
                mma_tf32(d[0], d[1], d[2], d[3], ah0, ah1, ah2, ah3, bh[nt][0], bh[nt][1]);
            }
        }
    }
    __syncthreads();   // GEMM done (AH free); exchange K-half partials

    // ---- merge K halves: lower warps keep mt 0..1, upper keep mt 2..3 ----
    {
        float4* exch = (float4*)(sm + OFF_AH);   // 256 x 4 float4 = 16KB
        const int send = (tid < 128) ? 2 : 0;    // mts this thread sends away
#pragma unroll
        for (int j = 0; j < 2; j++)
#pragma unroll
            for (int nt = 0; nt < 2; nt++) {
                const float* d = acc[send + j][nt];
                exch[(j * 2 + nt) * 256 + tid] = make_float4(d[0], d[1], d[2], d[3]);
            }
        __syncthreads();
        const int p    = tid ^ 128;
        const int keep = (tid < 128) ? 0 : 2;
#pragma unroll
        for (int j = 0; j < 2; j++)
#pragma unroll
            for (int nt = 0; nt < 2; nt++) {
                float4 r = exch[(j * 2 + nt) * 256 + p];
                float* d = acc[keep + j][nt];
                d[0] += r.x; d[1] += r.y; d[2] += r.z; d[3] += r.w;
            }
    }

    // thread now owns rows mtK*16+g / +8 for mtK in {keep, keep+1}
    const int keep = (tid < 128) ? 0 : 2;

    // ---- epilogue: e = exp(sims/128), no max subtraction ----
    const float inv128 = 1.0f / 128.0f;
#pragma unroll
    for (int j = 0; j < 2; j++)
#pragma unroll
        for (int nt = 0; nt < 2; nt++)
#pragma unroll
            for (int qq = 0; qq < 4; qq++)
                acc[keep + j][nt][qq] = __expf(acc[keep + j][nt][qq] * inv128);

    // row partial sums (this warp's 16 cols) -> rowpart[row*4 + wc]
#pragma unroll
    for (int j = 0; j < 2; j++) {
        const int mtK = keep + j;
        float r0 = acc[mtK][0][0] + acc[mtK][0][1] + acc[mtK][1][0] + acc[mtK][1][1];
        float r1 = acc[mtK][0][2] + acc[mtK][0][3] + acc[mtK][1][2] + acc[mtK][1][3];
        r0 += __shfl_xor_sync(0xffffffffu, r0, 1);
        r0 += __shfl_xor_sync(0xffffffffu, r0, 2);
        r1 += __shfl_xor_sync(0xffffffffu, r1, 1);
        r1 += __shfl_xor_sync(0xffffffffu, r1, 2);
        if (tig == 0) {
            int row = mtK * 16 + g;
            rowpart[row * 4 + wc]       = r0;
            rowpart[(row + 8) * 4 + wc] = r1;
        }
    }
    // col partial sums (this warp's 32 kept rows) -> colpart[(warp>>2)*64 + col]
#pragma unroll
    for (int nt = 0; nt < 2; nt++) {
        float c0 = acc[keep][nt][0] + acc[keep][nt][2] +
                   acc[keep + 1][nt][0] + acc[keep + 1][nt][2];
        float c1 = acc[keep][nt][1] + acc[keep][nt][3] +
                   acc[keep + 1][nt][1] + acc[keep + 1][nt][3];
        c0 += __shfl_xor_sync(0xffffffffu, c0, 4);
        c0 += __shfl_xor_sync(0xffffffffu, c0, 8);
        c0 += __shfl_xor_sync(0xffffffffu, c0, 16);
        c1 += __shfl_xor_sync(0xffffffffu, c1, 4);
        c1 += __shfl_xor_sync(0xffffffffu, c1, 8);
        c1 += __shfl_xor_sync(0xffffffffu, c1, 16);
        if (g == 0)
            *(float2*)(colpart + (warp >> 2) * 64 + wc * 16 + nt * 8 + 2 * tig) =
                make_float2(c0, c1);
    }
    __syncthreads();
    if (tid < 64) {
        const float4* rp = (const float4*)(rowpart + tid * 4);
        float4 p = rp[0];
        rinv_s[tid] = 1.0f / ((p.x + p.y) + (p.z + p.w));
    } else if (tid < 128) {
        int c = tid - 64;
        cinv_s[c] = 1.0f / (colpart[c] + colpart[64 + c]);
    }
    __syncthreads();

    // h-pass: h = e*e*rinv[row]*cinv[col]; store + masked argmax
    float rin[2][2];
#pragma unroll
    for (int j = 0; j < 2; j++) {
        rin[j][0] = rinv_s[(keep + j) * 16 + g];
        rin[j][1] = rinv_s[(keep + j) * 16 + g + 8];
    }
    float2 cin[2];
    bool mcol[2][2];
#pragma unroll
    for (int nt = 0; nt < 2; nt++) {
        int c = wc * 16 + nt * 8 + 2 * tig;
        cin[nt] = *(const float2*)(cinv_s + c);
        mcol[nt][0] = inner_mask(c);
        mcol[nt][1] = inner_mask(c + 1);
    }

    float bestv = -1.0f;
    int   besti = 0;
    float* hmbase = hm + (size_t)m * 4096;
#pragma unroll
    for (int j = 0; j < 2; j++) {
        const int mtK = keep + j;
        int row0 = mtK * 16 + g;
        bool mr0 = inner_mask(row0);
        bool mr1 = inner_mask(row0 + 8);
#pragma unroll
        for (int nt = 0; nt < 2; nt++) {
            int col0 = wc * 16 + nt * 8 + 2 * tig;
            float h0 = acc[mtK][nt][0] * acc[mtK][nt][0] * rin[j][0] * cin[nt].x;
            float h1 = acc[mtK][nt][1] * acc[mtK][nt][1] * rin[j][0] * cin[nt].y;
            float h2 = acc[mtK][nt][2] * acc[mtK][nt][2] * rin[j][1] * cin[nt].x;
            float h3 = acc[mtK][nt][3] * acc[mtK][nt][3] * rin[j][1] * cin[nt].y;
            *(float2*)(hmbase + row0 * 64 + col0)       = make_float2(h0, h1);
            *(float2*)(hmbase + (row0 + 8) * 64 + col0) = make_float2(h2, h3);
            if (mr0) {
                if (mcol[nt][0]) {
                    int fi = (row0 << 6) | col0;
                    if (h0 > bestv || (h0 == bestv && fi < besti)) { bestv = h0; besti = fi; }
                }
                if (mcol[nt][1]) {
                    int fi = (row0 << 6) | (col0 + 1);
                    if (h1 > bestv || (h1 == bestv && fi < besti)) { bestv = h1; besti = fi; }
                }
            }
            if (mr1) {
                if (mcol[nt][0]) {
                    int fi = ((row0 + 8) << 6) | col0;
                    if (h2 > bestv || (h2 == bestv && fi < besti)) { bestv = h2; besti = fi; }
                }
                if (mcol[nt][1]) {
                    int fi = ((row0 + 8) << 6) | (col0 + 1);
                    if (h3 > bestv || (h3 == bestv && fi < besti)) { bestv = h3; besti = fi; }
                }
            }
        }
    }

    // warp argmax reduce (min flat idx on ties)
#pragma unroll
    for (int off = 16; off >= 1; off >>= 1) {
        float ov = __shfl_xor_sync(0xffffffffu, bestv, off);
        int   oi = __shfl_xor_sync(0xffffffffu, besti, off);
        if (ov > bestv || (ov == bestv && oi < besti)) { bestv = ov; besti = oi; }
    }
    if (lane == 0) { redv[warp] = bestv; redi[warp] = besti; }
    __syncthreads();
    if (tid == 0) {
        float bv = redv[0];
        int   bx = redi[0];
#pragma unroll
        for (int w = 1; w < 8; w++) {
            float ov = redv[w];
            int   oi = redi[w];
            if (ov > bv || (ov == bv && oi < bx)) { bv = ov; bx = oi; }
        }
        int il = bx >> 6;
        int is = bx & 63;
        oil[m] = (float)il;
        ois[m] = (float)is;
        ob0[2 * m + 0] = (float)(il & 7) - 3.5f;
        ob0[2 * m + 1] = (float)(il >> 3) - 3.5f;
        ob1[2 * m + 0] = (float)(is & 7) - 3.5f;
        ob1[2 * m + 1] = (float)(is >> 3) - 3.5f;
    }
}

extern "C" void kernel_launch(void* const* d_in, const int* in_sizes, int n_in,
                              void* d_out, int out_size) {
    const float* x0 = (const float*)d_in[0];
    const float* x1 = (const float*)d_in[1];
    const int M = in_sizes[0] / (64 * 128);

    float* out = (float*)d_out;
    float* hm  = out;
    float* oil = hm + (size_t)M * 4096;
    float* ois = oil + M;
    float* ob0 = ois + M;
    float* ob1 = ob0 + 2 * (size_t)M;

    cudaFuncSetAttribute(fm_kernel, cudaFuncAttributeMaxDynamicSharedMemorySize,
                         SMEM_BYTES);
    fm_kernel<<<M, NTHREADS, SMEM_BYTES>>>(x0, x1, hm, oil, ois, ob0, ob1);
}

// round 11
// speedup vs baseline: 1.0463x; 1.0463x over previous
#include <cuda_runtime.h>
#include <cuda_fp16.h>
#include <cstdint>

// FineMatching: per match m (grid.x):
//   sims[l][s] = dot(x0[m,l,:], x1[m,s,:]) / 128
//   heatmap    = softmax_l(sims) * softmax_s(sims); masked argmax -> idx/biases
//
// d_out (f32): [ heatmap M*4096 | idx_l M | idx_s M | biases0 2M | biases1 2M ]
//
// Round-11: fp16 limb-extension GEMM. x scaled by 2^8, split into fp16 limbs
// h1,h2 (11-bit mantissa each == tf32 precision). K extended 3x with patterns
// A_ext=[h1,h1,h2], B_ext=[g1,g2,g1] so one fp16 m16n8k16 dot over K_ext=384
// computes h1g1+h1g2+h2g1 per k — same 3 products as 3xTF32, half the mma
// instructions, no in-GEMM splits. 128 thr, 4 warps x 16 cols, 2 CTAs/SM.

#define NTHREADS 128

// ---- smem byte offsets ----
#define OFF_A  0                    // 64 rows x 768B (384 fp16), XOR-chunk swizzled
#define OFF_B  49152                // same
#define OFF_RP 98304                // row partials: 64 x 4 f32
#define OFF_CS (OFF_RP + 1024)      // csum 64 f32
#define OFF_CI (OFF_CS + 256)       // cinv 64 f32
#define OFF_RI (OFF_CI + 256)       // rinv 64 f32
#define OFF_RV (OFF_RI + 256)       // 4 f32
#define OFF_RX (OFF_RV + 16)        // 4 i32
#define SMEM_BYTES (OFF_RX + 16)

__device__ __forceinline__ uint32_t smem_u32(const void* p) {
    uint32_t a;
    asm("{ .reg .u64 t; cvta.to.shared.u64 t, %1; cvt.u32.u64 %0, t; }" : "=r"(a) : "l"(p));
    return a;
}

__device__ __forceinline__ uint32_t packh(__half lo, __half hi) {
    return (uint32_t)__half_as_ushort(lo) | ((uint32_t)__half_as_ushort(hi) << 16);
}

__device__ __forceinline__ void ldsm_x4(uint32_t& r0, uint32_t& r1, uint32_t& r2,
                                        uint32_t& r3, uint32_t addr) {
    asm volatile("ldmatrix.sync.aligned.m8n8.x4.shared.b16 {%0,%1,%2,%3}, [%4];"
                 : "=r"(r0), "=r"(r1), "=r"(r2), "=r"(r3) : "r"(addr));
}

__device__ __forceinline__ void mma_f16(float& d0, float& d1, float& d2, float& d3,
                                        uint32_t a0, uint32_t a1, uint32_t a2, uint32_t a3,
                                        uint32_t b0, uint32_t b1) {
    asm volatile(
        "mma.sync.aligned.m16n8k16.row.col.f32.f16.f16.f32 "
        "{%0,%1,%2,%3}, {%4,%5,%6,%7}, {%8,%9}, {%0,%1,%2,%3};"
        : "+f"(d0), "+f"(d1), "+f"(d2), "+f"(d3)
        : "r"(a0), "r"(a1), "r"(a2), "r"(a3), "r"(b0), "r"(b1));
}

__device__ __forceinline__ bool inner_mask(int p) {
    int y = p >> 3, x = p & 7;
    return (y >= 1) & (y <= 6) & (x >= 1) & (x <= 6);
}

// split scaled X into fp16 limbs
__device__ __forceinline__ void limb2(float X, __half& h1, __half& h2) {
    h1 = __float2half_rn(X);
    h2 = __float2half_rn(X - __half2float(h1));
}

__global__ void __launch_bounds__(NTHREADS, 2)
fm_kernel(const float* __restrict__ x0, const float* __restrict__ x1,
          float* __restrict__ hm, float* __restrict__ oil,
          float* __restrict__ ois, float* __restrict__ ob0,
          float* __restrict__ ob1) {
    extern __shared__ char sm[];
    float* rowpart = (float*)(sm + OFF_RP);
    float* csum_s  = (float*)(sm + OFF_CS);
    float* cinv_s  = (float*)(sm + OFF_CI);
    float* rinv_s  = (float*)(sm + OFF_RI);
    float* redv    = (float*)(sm + OFF_RV);
    int*   redi    = (int*)(sm + OFF_RX);

    const int m    = blockIdx.x;
    const int tid  = threadIdx.x;
    const int warp = tid >> 5;
    const int lane = tid & 31;
    const int g    = lane >> 2;
    const int tig  = lane & 3;

    // ---- stage: scale by 2^8, split to limbs, write K-extended planes ----
    // group = 8 consecutive k of one row -> 24 limbs = 3 swizzled 16B chunks
    {
        const float4* p0 = (const float4*)(x0 + (size_t)m * 8192);
        const float4* p1 = (const float4*)(x1 + (size_t)m * 8192);
#pragma unroll
        for (int it = 0; it < 8; it++) {
            int gi = tid + it * NTHREADS;      // group idx 0..1023
            int r  = gi >> 4;                  // row 0..63
            int G  = gi & 15;                  // group in row
            uint32_t base = r * 768;
            uint32_t swz  = (uint32_t)((r & 7) << 4);
            uint32_t cb   = (uint32_t)(G * 48);

            // ---- A (pattern [h1,h1,h2]) ----
            {
                float4 fa = p0[gi * 2], fb = p0[gi * 2 + 1];
                float X[8] = {fa.x, fa.y, fa.z, fa.w, fb.x, fb.y, fb.z, fb.w};
                __half h1[8], h2[8];
#pragma unroll
                for (int e = 0; e < 8; e++) limb2(X[e] * 256.0f, h1[e], h2[e]);
                uint32_t w[12];
#pragma unroll
                for (int e2 = 0; e2 < 4; e2++) {
                    int a = 2 * e2, b = a + 1;
                    w[3 * e2 + 0] = packh(h1[a], h1[a]);
                    w[3 * e2 + 1] = packh(h2[a], h1[b]);
                    w[3 * e2 + 2] = packh(h1[b], h2[b]);
                }
                char* pA = sm + OFF_A + base;
                *(uint4*)(pA + ((cb)      ^ swz)) = make_uint4(w[0], w[1], w[2], w[3]);
                *(uint4*)(pA + ((cb + 16) ^ swz)) = make_uint4(w[4], w[5], w[6], w[7]);
                *(uint4*)(pA + ((cb + 32) ^ swz)) = make_uint4(w[8], w[9], w[10], w[11]);
            }
            // ---- B (pattern [g1,g2,g1]) ----
            {
                float4 fa = p1[gi * 2], fb = p1[gi * 2 + 1];
                float X[8] = {fa.x, fa.y, fa.z, fa.w, fb.x, fb.y, fb.z, fb.w};
                __half h1[8], h2[8];
#pragma unroll
                for (int e = 0; e < 8; e++) limb2(X[e] * 256.0f, h1[e], h2[e]);
                uint32_t w[12];
#pragma unroll
                for (int e2 = 0; e2 < 4; e2++) {
                    int a = 2 * e2, b = a + 1;
                    w[3 * e2 + 0] = packh(h1[a], h2[a]);
                    w[3 * e2 + 1] = packh(h1[a], h1[b]);
                    w[3 * e2 + 2] = packh(h2[b], h1[b]);
                }
                char* pB = sm + OFF_B + base;
                *(uint4*)(pB + ((cb)      ^ swz)) = make_uint4(w[0], w[1], w[2], w[3]);
                *(uint4*)(pB + ((cb + 16) ^ swz)) = make_uint4(w[4], w[5], w[6], w[7]);
                *(uint4*)(pB + ((cb + 32) ^ swz)) = make_uint4(w[8], w[9], w[10], w[11]);
            }
        }
    }
    __syncthreads();

    // ---- GEMM: warp w -> sims[0:64, w*16:(w+1)*16], fp16 K_ext=384 ----
    float acc[4][2][4];
#pragma unroll
    for (int mt = 0; mt < 4; mt++)
#pragma unroll
        for (int nt = 0; nt < 2; nt++)
#pragma unroll
            for (int qq = 0; qq < 4; qq++) acc[mt][nt][qq] = 0.0f;

    const uint32_t smb = smem_u32(sm);
    const int qm = lane >> 3;
    const int rm = lane & 7;
    const uint32_t kq = (uint32_t)((qm >> 1) << 4);
    uint32_t abase[4], axm[4];
#pragma unroll
    for (int mt = 0; mt < 4; mt++) {
        int row = mt * 16 + ((qm & 1) << 3) + rm;
        abase[mt] = smb + OFF_A + row * 768;
        axm[mt]   = (uint32_t)((row & 7) << 4);
    }
    uint32_t bbase[2], bswz[2];
#pragma unroll
    for (int nt = 0; nt < 2; nt++) {
        int srow = warp * 16 + nt * 8 + g;
        bbase[nt] = OFF_B + srow * 768 + tig * 4;
        bswz[nt]  = (uint32_t)((srow & 7) << 4);
    }

#pragma unroll 4
    for (int kt = 0; kt < 24; kt++) {
        uint32_t c0 = (uint32_t)(kt * 32);
        uint32_t b0[2], b1[2];
#pragma unroll
        for (int nt = 0; nt < 2; nt++) {
            b0[nt] = *(const uint32_t*)(sm + bbase[nt] + (c0 ^ bswz[nt]));
            b1[nt] = *(const uint32_t*)(sm + bbase[nt] + ((c0 + 16) ^ bswz[nt]));
        }
#pragma unroll
        for (int mt = 0; mt < 4; mt++) {
            uint32_t ad = abase[mt] + ((c0 + kq) ^ axm[mt]);
            uint32_t a0, a1, a2, a3;
            ldsm_x4(a0, a1, a2, a3, ad);
#pragma unroll
            for (int nt = 0; nt < 2; nt++) {
                float* d = acc[mt][nt];
                mma_f16(d[0], d[1], d[2], d[3], a0, a1, a2, a3, b0[nt], b1[nt]);
            }
        }
    }

    // ---- epilogue in acc layout (e = exp(acc * 2^-23), no max) ----
    const float invs = 1.0f / 8388608.0f;   // 1/(128 * 2^16)
#pragma unroll
    for (int mt = 0; mt < 4; mt++)
#pragma unroll
        for (int nt = 0; nt < 2; nt++)
#pragma unroll
            for (int qq = 0; qq < 4; qq++)
                acc[mt][nt][qq] = __expf(acc[mt][nt][qq] * invs);

    // row partial sums (this warp's 16 cols) -> rowpart[row*4 + warp]
#pragma unroll
    for (int mt = 0; mt < 4; mt++) {
        float r0 = acc[mt][0][0] + acc[mt][0][1] + acc[mt][1][0] + acc[mt][1][1];
        float r1 = acc[mt][0][2] + acc[mt][0][3] + acc[mt][1][2] + acc[mt][1][3];
        r0 += __shfl_xor_sync(0xffffffffu, r0, 1);
        r0 += __shfl_xor_sync(0xffffffffu, r0, 2);
        r1 += __shfl_xor_sync(0xffffffffu, r1, 1);
        r1 += __shfl_xor_sync(0xffffffffu, r1, 2);
        if (tig == 0) {
            rowpart[(mt * 16 + g) * 4 + warp]     = r0;
            rowpart[(mt * 16 + g + 8) * 4 + warp] = r1;
        }
    }
    // col sums (all 64 rows, in-warp)
#pragma unroll
    for (int nt = 0; nt < 2; nt++) {
        float c0 = acc[0][nt][0] + acc[0][nt][2];
        float c1 = acc[0][nt][1] + acc[0][nt][3];
#pragma unroll
        for (int mt = 1; mt < 4; mt++) {
            c0 += acc[mt][nt][0] + acc[mt][nt][2];
            c1 += acc[mt][nt][1] + acc[mt][nt][3];
        }
        c0 += __shfl_xor_sync(0xffffffffu, c0, 4);
        c0 += __shfl_xor_sync(0xffffffffu, c0, 8);
        c0 += __shfl_xor_sync(0xffffffffu, c0, 16);
        c1 += __shfl_xor_sync(0xffffffffu, c1, 4);
        c1 += __shfl_xor_sync(0xffffffffu, c1, 8);
        c1 += __shfl_xor_sync(0xffffffffu, c1, 16);
        if (g == 0)
            *(float2*)(csum_s + warp * 16 + nt * 8 + 2 * tig) = make_float2(c0, c1);
    }
    __syncthreads();
    if (tid < 64) {
        const float4* rp = (const float4*)(rowpart + tid * 4);
        float4 p = rp[0];
        rinv_s[tid] = 1.0f / ((p.x + p.y) + (p.z + p.w));
    } else {
        int c = tid - 64;
        cinv_s[c] = 1.0f / csum_s[c];
    }
    __syncthreads();

    // h-pass: h = e*e*rinv[row]*cinv[col]; store + masked argmax
    float rin[4][2];
#pragma unroll
    for (int mt = 0; mt < 4; mt++) {
        rin[mt][0] = rinv_s[mt * 16 + g];
        rin[mt][1] = rinv_s[mt * 16 + g + 8];
    }
    float2 cin[2];
    bool mcol[2][2];
#pragma unroll
    for (int nt = 0; nt < 2; nt++) {
        int c = warp * 16 + nt * 8 + 2 * tig;
        cin[nt] = *(const float2*)(cinv_s + c);
        mcol[nt][0] = inner_mask(c);
        mcol[nt][1] = inner_mask(c + 1);
    }

    float bestv = -1.0f;
    int   besti = 0;
    float* hmbase = hm + (size_t)m * 4096;
#pragma unroll
    for (int mt = 0; mt < 4; mt++) {
        int row0 = mt * 16 + g;
        bool mr0 = inner_mask(row0);
        bool mr1 = inner_mask(row0 + 8);
#pragma unroll
        for (int nt = 0; nt < 2; nt++) {
            int col0 = warp * 16 + nt * 8 + 2 * tig;
            float h0 = acc[mt][nt][0] * acc[mt][nt][0] * rin[mt][0] * cin[nt].x;
            float h1 = acc[mt][nt][1] * acc[mt][nt][1] * rin[mt][0] * cin[nt].y;
            float h2 = acc[mt][nt][2] * acc[mt][nt][2] * rin[mt][1] * cin[nt].x;
            float h3 = acc[mt][nt][3] * acc[mt][nt][3] * rin[mt][1] * cin[nt].y;
            *(float2*)(hmbase + row0 * 64 + col0)       = make_float2(h0, h1);
            *(float2*)(hmbase + (row0 + 8) * 64 + col0) = make_float2(h2, h3);
            if (mr0) {
                if (mcol[nt][0]) {
                    int fi = (row0 << 6) | col0;
                    if (h0 > bestv || (h0 == bestv && fi < besti)) { bestv = h0; besti = fi; }
                }
                if (mcol[nt][1]) {
                    int fi = (row0 << 6) | (col0 + 1);
                    if (h1 > bestv || (h1 == bestv && fi < besti)) { bestv = h1; besti = fi; }
                }
            }
            if (mr1) {
                if (mcol[nt][0]) {
                    int fi = ((row0 + 8) << 6) | col0;
                    if (h2 > bestv || (h2 == bestv && fi < besti)) { bestv = h2; besti = fi; }
                }
                if (mcol[nt][1]) {
                    int fi = ((row0 + 8) << 6) | (col0 + 1);
                    if (h3 > bestv || (h3 == bestv && fi < besti)) { bestv = h3; besti = fi; }
                }
            }
        }
    }

    // block argmax (min flat idx on ties)
#pragma unroll
    for (int off = 16; off >= 1; off >>= 1) {
        float ov = __shfl_xor_sync(0xffffffffu, bestv, off);
        int   oi = __shfl_xor_sync(0xffffffffu, besti, off);
        if (ov > bestv || (ov == bestv && oi < besti)) { bestv = ov; besti = oi; }
    }
    if (lane == 0) { redv[warp] = bestv; redi[warp] = besti; }
    __syncthreads();
    if (tid == 0) {
        float bv = redv[0];
        int   bx = redi[0];
#pragma unroll
        for (int w = 1; w < 4; w++) {
            float ov = redv[w];
            int   oi = redi[w];
            if (ov > bv || (ov == bv && oi < bx)) { bv = ov; bx = oi; }
        }
        int il = bx >> 6;
        int is = bx & 63;
        oil[m] = (float)il;
        ois[m] = (float)is;
        ob0[2 * m + 0] = (float)(il & 7) - 3.5f;
        ob0[2 * m + 1] = (float)(il >> 3) - 3.5f;
        ob1[2 * m + 0] = (float)(is & 7) - 3.5f;
        ob1[2 * m + 1] = (float)(is >> 3) - 3.5f;
    }
}

extern "C" void kernel_launch(void* const* d_in, const int* in_sizes, int n_in,
                              void* d_out, int out_size) {
    const float* x0 = (const float*)d_in[0];
    const float* x1 = (const float*)d_in[1];
    const int M = in_sizes[0] / (64 * 128);

    float* out = (float*)d_out;
    float* hm  = out;
    float* oil = hm + (size_t)M * 4096;
    float* ois = oil + M;
    float* ob0 = ois + M;
    float* ob1 = ob0 + 2 * (size_t)M;

    cudaFuncSetAttribute(fm_kernel, cudaFuncAttributeMaxDynamicSharedMemorySize,
                         SMEM_BYTES);
    fm_kernel<<<M, NTHREADS, SMEM_BYTES>>>(x0, x1, hm, oil, ois, ob0, ob1);
}

// round 13
// speedup vs baseline: 1.5192x; 1.4520x over previous
#include <cuda_runtime.h>
#include <cuda_fp16.h>
#include <cstdint>

// FineMatching: per match m (grid.x):
//   sims[l][s] = dot(x0[m,l,:], x1[m,s,:]) / 128
//   heatmap    = softmax_l(sims) * softmax_s(sims); masked argmax -> idx/biases
//
// d_out (f32): [ heatmap M*4096 | idx_l M | idx_s M | biases0 2M | biases1 2M ]
//
// Round-13 (= round-12 + bitcast fix): fp16 two-limb GEMM via 3 plane-pair
// products. x*256 split into fp16 limbs h1,h2 stored in 4 separate swizzled
// planes (16KB each). Per k-step: A1,A2 ldsm + B1,B2 frags; mma A1*B1 +
// A1*B2 + A2*B1 (same products as 3xTF32, rel err ~2e-7). 64KB smem ->
// 3 CTAs/SM; minimal instruction count.

#define NTHREADS 128

// ---- smem byte offsets ----
#define OFF_AP1 0                    // A h1 plane: 64 rows x 256B, XOR-swizzled
#define OFF_AP2 16384                // A h2
#define OFF_BP1 32768                // B g1
#define OFF_BP2 49152                // B g2
#define OFF_RP  65536                // row partials: 64 x 4 f32
#define OFF_CS  (OFF_RP + 1024)     // csum 64 f32
#define OFF_CI  (OFF_CS + 256)      // cinv 64 f32
#define OFF_RI  (OFF_CI + 256)      // rinv 64 f32
#define OFF_RV  (OFF_RI + 256)      // 4 f32
#define OFF_RX  (OFF_RV + 16)       // 4 i32
#define SMEM_BYTES (OFF_RX + 16)

__device__ __forceinline__ uint32_t smem_u32(const void* p) {
    uint32_t a;
    asm("{ .reg .u64 t; cvta.to.shared.u64 t, %1; cvt.u32.u64 %0, t; }" : "=r"(a) : "l"(p));
    return a;
}

__device__ __forceinline__ uint32_t h2_bits(__half2 h) {
    union { __half2 h; uint32_t u; } c;
    c.h = h;
    return c.u;
}

__device__ __forceinline__ void ldsm_x4(uint32_t& r0, uint32_t& r1, uint32_t& r2,
                                        uint32_t& r3, uint32_t addr) {
    asm volatile("ldmatrix.sync.aligned.m8n8.x4.shared.b16 {%0,%1,%2,%3}, [%4];"
                 : "=r"(r0), "=r"(r1), "=r"(r2), "=r"(r3) : "r"(addr));
}

__device__ __forceinline__ void mma_f16(float& d0, float& d1, float& d2, float& d3,
                                        uint32_t a0, uint32_t a1, uint32_t a2, uint32_t a3,
                                        uint32_t b0, uint32_t b1) {
    asm volatile(
        "mma.sync.aligned.m16n8k16.row.col.f32.f16.f16.f32 "
        "{%0,%1,%2,%3}, {%4,%5,%6,%7}, {%8,%9}, {%0,%1,%2,%3};"
        : "+f"(d0), "+f"(d1), "+f"(d2), "+f"(d3)
        : "r"(a0), "r"(a1), "r"(a2), "r"(a3), "r"(b0), "r"(b1));
}

__device__ __forceinline__ bool inner_mask(int p) {
    int y = p >> 3, x = p & 7;
    return (y >= 1) & (y <= 6) & (x >= 1) & (x <= 6);
}

// split 4 scaled floats into packed h1 (uint2) and h2 (uint2) limb pairs
__device__ __forceinline__ void limb4(float4 f, uint2& w1, uint2& w2) {
    float2 xy = make_float2(f.x * 256.0f, f.y * 256.0f);
    float2 zw = make_float2(f.z * 256.0f, f.w * 256.0f);
    __half2 h1a = __float22half2_rn(xy);
    __half2 h1b = __float22half2_rn(zw);
    float2 b1 = __half22float2(h1a);
    float2 b2 = __half22float2(h1b);
    __half2 h2a = __float22half2_rn(make_float2(xy.x - b1.x, xy.y - b1.y));
    __half2 h2b = __float22half2_rn(make_float2(zw.x - b2.x, zw.y - b2.y));
    w1 = make_uint2(h2_bits(h1a), h2_bits(h1b));
    w2 = make_uint2(h2_bits(h2a), h2_bits(h2b));
}

__global__ void __launch_bounds__(NTHREADS, 3)
fm_kernel(const float* __restrict__ x0, const float* __restrict__ x1,
          float* __restrict__ hm, float* __restrict__ oil,
          float* __restrict__ ois, float* __restrict__ ob0,
          float* __restrict__ ob1) {
    extern __shared__ char sm[];
    float* rowpart = (float*)(sm + OFF_RP);
    float* csum_s  = (float*)(sm + OFF_CS);
    float* cinv_s  = (float*)(sm + OFF_CI);
    float* rinv_s  = (float*)(sm + OFF_RI);
    float* redv    = (float*)(sm + OFF_RV);
    int*   redi    = (int*)(sm + OFF_RX);

    const int m    = blockIdx.x;
    const int tid  = threadIdx.x;
    const int warp = tid >> 5;
    const int lane = tid & 31;
    const int g    = lane >> 2;
    const int tig  = lane & 3;

    // ---- stage: split to limbs, write 4 planes (rows 256B, XOR-swizzled) ----
    {
        const float4* p0 = (const float4*)(x0 + (size_t)m * 8192);
        const float4* p1 = (const float4*)(x1 + (size_t)m * 8192);
#pragma unroll
        for (int it = 0; it < 16; it++) {
            int i   = tid + it * NTHREADS;      // float4 idx 0..2047
            int row = i >> 5;                   // 0..63
            int q   = i & 31;                   // float4 within row
            uint32_t off = (uint32_t)(row * 256) +
                           (((uint32_t)(q * 8)) ^ (uint32_t)((row & 7) << 4));
            uint2 w1, w2;
            limb4(p0[i], w1, w2);
            *(uint2*)(sm + OFF_AP1 + off) = w1;
            *(uint2*)(sm + OFF_AP2 + off) = w2;
            limb4(p1[i], w1, w2);
            *(uint2*)(sm + OFF_BP1 + off) = w1;
            *(uint2*)(sm + OFF_BP2 + off) = w2;
        }
    }
    __syncthreads();

    // ---- GEMM: warp w -> sims[0:64, w*16:(w+1)*16] ----
    float acc[4][2][4];
#pragma unroll
    for (int mt = 0; mt < 4; mt++)
#pragma unroll
        for (int nt = 0; nt < 2; nt++)
#pragma unroll
            for (int qq = 0; qq < 4; qq++) acc[mt][nt][qq] = 0.0f;

    const uint32_t smb = smem_u32(sm);
    const int qm = lane >> 3;
    const int rm = lane & 7;
    const uint32_t kq = (uint32_t)((qm >> 1) << 4);
    uint32_t abase[4], axm[4];
#pragma unroll
    for (int mt = 0; mt < 4; mt++) {
        int row = mt * 16 + ((qm & 1) << 3) + rm;
        abase[mt] = smb + OFF_AP1 + row * 256;
        axm[mt]   = (uint32_t)((row & 7) << 4);
    }
    uint32_t b1base[2], b2base[2], bswz[2];
#pragma unroll
    for (int nt = 0; nt < 2; nt++) {
        int srow = warp * 16 + nt * 8 + g;
        b1base[nt] = OFF_BP1 + srow * 256 + tig * 4;
        b2base[nt] = OFF_BP2 + srow * 256 + tig * 4;
        bswz[nt]   = (uint32_t)((srow & 7) << 4);
    }

#pragma unroll
    for (int kt = 0; kt < 8; kt++) {
        uint32_t c0 = (uint32_t)(kt << 5);
        uint32_t c1 = c0 + 16;
        // B fragments from both planes
        uint32_t q10[2], q11[2], q20[2], q21[2];
#pragma unroll
        for (int nt = 0; nt < 2; nt++) {
            q10[nt] = *(const uint32_t*)(sm + b1base[nt] + (c0 ^ bswz[nt]));
            q11[nt] = *(const uint32_t*)(sm + b1base[nt] + (c1 ^ bswz[nt]));
            q20[nt] = *(const uint32_t*)(sm + b2base[nt] + (c0 ^ bswz[nt]));
            q21[nt] = *(const uint32_t*)(sm + b2base[nt] + (c1 ^ bswz[nt]));
        }
#pragma unroll
        for (int mt = 0; mt < 4; mt++) {
            uint32_t ad = abase[mt] + ((c0 + kq) ^ axm[mt]);
            uint32_t a10, a11, a12, a13, a20, a21, a22, a23;
            ldsm_x4(a10, a11, a12, a13, ad);            // A h1
            ldsm_x4(a20, a21, a22, a23, ad + 16384);    // A h2
#pragma unroll
            for (int nt = 0; nt < 2; nt++) {
                float* d = acc[mt][nt];
                mma_f16(d[0], d[1], d[2], d[3], a10, a11, a12, a13, q10[nt], q11[nt]); // h1g1
                mma_f16(d[0], d[1], d[2], d[3], a10, a11, a12, a13, q20[nt], q21[nt]); // h1g2
                mma_f16(d[0], d[1], d[2], d[3], a20, a21, a22, a23, q10[nt], q11[nt]); // h2g1
            }
        }
    }

    // ---- epilogue in acc layout (e = exp(acc * 2^-23), no max) ----
    const float invs = 1.0f / 8388608.0f;   // 1/(128 * 2^16)
#pragma unroll
    for (int mt = 0; mt < 4; mt++)
#pragma unroll
        for (int nt = 0; nt < 2; nt++)
#pragma unroll
            for (int qq = 0; qq < 4; qq++)
                acc[mt][nt][qq] = __expf(acc[mt][nt][qq] * invs);

    // row partial sums (this warp's 16 cols) -> rowpart[row*4 + warp]
#pragma unroll
    for (int mt = 0; mt < 4; mt++) {
        float r0 = acc[mt][0][0] + acc[mt][0][1] + acc[mt][1][0] + acc[mt][1][1];
        float r1 = acc[mt][0][2] + acc[mt][0][3] + acc[mt][1][2] + acc[mt][1][3];
        r0 += __shfl_xor_sync(0xffffffffu, r0, 1);
        r0 += __shfl_xor_sync(0xffffffffu, r0, 2);
        r1 += __shfl_xor_sync(0xffffffffu, r1, 1);
        r1 += __shfl_xor_sync(0xffffffffu, r1, 2);
        if (tig == 0) {
            rowpart[(mt * 16 + g) * 4 + warp]     = r0;
            rowpart[(mt * 16 + g + 8) * 4 + warp] = r1;
        }
    }
    // col sums (all 64 rows, in-warp)
#pragma unroll
    for (int nt = 0; nt < 2; nt++) {
        float c0 = acc[0][nt][0] + acc[0][nt][2];
        float c1 = acc[0][nt][1] + acc[0][nt][3];
#pragma unroll
        for (int mt = 1; mt < 4; mt++) {
            c0 += acc[mt][nt][0] + acc[mt][nt][2];
            c1 += acc[mt][nt][1] + acc[mt][nt][3];
        }
        c0 += __shfl_xor_sync(0xffffffffu, c0, 4);
        c0 += __shfl_xor_sync(0xffffffffu, c0, 8);
        c0 += __shfl_xor_sync(0xffffffffu, c0, 16);
        c1 += __shfl_xor_sync(0xffffffffu, c1, 4);
        c1 += __shfl_xor_sync(0xffffffffu, c1, 8);
        c1 += __shfl_xor_sync(0xffffffffu, c1, 16);
        if (g == 0)
            *(float2*)(csum_s + warp * 16 + nt * 8 + 2 * tig) = make_float2(c0, c1);
    }
    __syncthreads();
    if (tid < 64) {
        const float4* rp = (const float4*)(rowpart + tid * 4);
        float4 p = rp[0];
        rinv_s[tid] = 1.0f / ((p.x + p.y) + (p.z + p.w));
    } else {
        int c = tid - 64;
        cinv_s[c] = 1.0f / csum_s[c];
    }
    __syncthreads();

    // h-pass: h = e*e*rinv[row]*cinv[col]; store + masked argmax
    float rin[4][2];
#pragma unroll
    for (int mt = 0; mt < 4; mt++) {
        rin[mt][0] = rinv_s[mt * 16 + g];
        rin[mt][1] = rinv_s[mt * 16 + g + 8];
    }
    float2 cin[2];
    bool mcol[2][2];
#pragma unroll
    for (int nt = 0; nt < 2; nt++) {
        int c = warp * 16 + nt * 8 + 2 * tig;
        cin[nt] = *(const float2*)(cinv_s + c);
        mcol[nt][0] = inner_mask(c);
        mcol[nt][1] = inner_mask(c + 1);
    }

    float bestv = -1.0f;
    int   besti = 0;
    float* hmbase = hm + (size_t)m * 4096;
#pragma unroll
    for (int mt = 0; mt < 4; mt++) {
        int row0 = mt * 16 + g;
        bool mr0 = inner_mask(row0);
        bool mr1 = inner_mask(row0 + 8);
#pragma unroll
        for (int nt = 0; nt < 2; nt++) {
            int col0 = warp * 16 + nt * 8 + 2 * tig;
            float h0 = acc[mt][nt][0] * acc[mt][nt][0] * rin[mt][0] * cin[nt].x;
            float h1 = acc[mt][nt][1] * acc[mt][nt][1] * rin[mt][0] * cin[nt].y;
            float h2 = acc[mt][nt][2] * acc[mt][nt][2] * rin[mt][1] * cin[nt].x;
            float h3 = acc[mt][nt][3] * acc[mt][nt][3] * rin[mt][1] * cin[nt].y;
            *(float2*)(hmbase + row0 * 64 + col0)       = make_float2(h0, h1);
            *(float2*)(hmbase + (row0 + 8) * 64 + col0) = make_float2(h2, h3);
            if (mr0) {
                if (mcol[nt][0]) {
                    int fi = (row0 << 6) | col0;
                    if (h0 > bestv || (h0 == bestv && fi < besti)) { bestv = h0; besti = fi; }
                }
                if (mcol[nt][1]) {
                    int fi = (row0 << 6) | (col0 + 1);
                    if (h1 > bestv || (h1 == bestv && fi < besti)) { bestv = h1; besti = fi; }
                }
            }
            if (mr1) {
                if (mcol[nt][0]) {
                    int fi = ((row0 + 8) << 6) | col0;
                    if (h2 > bestv || (h2 == bestv && fi < besti)) { bestv = h2; besti = fi; }
                }
                if (mcol[nt][1]) {
                    int fi = ((row0 + 8) << 6) | (col0 + 1);
                    if (h3 > bestv || (h3 == bestv && fi < besti)) { bestv = h3; besti = fi; }
                }
            }
        }
    }

    // block argmax (min flat idx on ties)
#pragma unroll
    for (int off = 16; off >= 1; off >>= 1) {
        float ov = __shfl_xor_sync(0xffffffffu, bestv, off);
        int   oi = __shfl_xor_sync(0xffffffffu, besti, off);
        if (ov > bestv || (ov == bestv && oi < besti)) { bestv = ov; besti = oi; }
    }
    if (lane == 0) { redv[warp] = bestv; redi[warp] = besti; }
    __syncthreads();
    if (tid == 0) {
        float bv = redv[0];
        int   bx = redi[0];
#pragma unroll
        for (int w = 1; w < 4; w++) {
            float ov = redv[w];
            int   oi = redi[w];
            if (ov > bv || (ov == bv && oi < bx)) { bv = ov; bx = oi; }
        }
        int il = bx >> 6;
        int is = bx & 63;
        oil[m] = (float)il;
        ois[m] = (float)is;
        ob0[2 * m + 0] = (float)(il & 7) - 3.5f;
        ob0[2 * m + 1] = (float)(il >> 3) - 3.5f;
        ob1[2 * m + 0] = (float)(is & 7) - 3.5f;
        ob1[2 * m + 1] = (float)(is >> 3) - 3.5f;
    }
}

extern "C" void kernel_launch(void* const* d_in, const int* in_sizes, int n_in,
                              void* d_out, int out_size) {
    const float* x0 = (const float*)d_in[0];
    const float* x1 = (const float*)d_in[1];
    const int M = in_sizes[0] / (64 * 128);

    float* out = (float*)d_out;
    float* hm  = out;
    float* oil = hm + (size_t)M * 4096;
    float* ois = oil + M;
    float* ob0 = ois + M;
    float* ob1 = ob0 + 2 * (size_t)M;

    cudaFuncSetAttribute(fm_kernel, cudaFuncAttributeMaxDynamicSharedMemorySize,
                         SMEM_BYTES);
    fm_kernel<<<M, NTHREADS, SMEM_BYTES>>>(x0, x1, hm, oil, ois, ob0, ob1);
}